// round 5
// baseline (speedup 1.0000x reference)
#include <cuda_runtime.h>
#include <cstdint>

// BinaryTree hierarchical-softmax forward:
//   z = W[leaf(input)], path = 21 root-to-leaf nodes of context vertex
//   out[b] = prod_i sigmoid(dot(W[path_i], z)) = 1 / prod_i (1 + exp(-s_i))
//
// d_in[0]: collocation int32 [65536, 2]
// d_in[1]: W float32 [2097151, 128]
// d_out  : float32 [65536]
//
// Persistent pipelined warps, one element per warp-iteration:
//   - coll prefetched 2 elements ahead
//   - pruned compaction transpose-reduce (23 shuffles; dead slots >= 21 skipped)
//   - the next element's 22-row LDG.128 burst is issued mid-reduce (after
//     stages 1-2, when the a[] live set has collapsed to 6), minimizing the
//     register peak so 5 blocks/SM fit (20 warps/SM of DRAM-level MLP).

#define DEPTH   20
#define NPATH   21
#define OFFSET  1048575u             // (1<<DEPTH)-1
#define NDIM    128
#define BATCH   65536

__global__ __launch_bounds__(128, 5)
void BinaryTree_65927747993695_kernel(const int* __restrict__ coll,
                                      const float* __restrict__ W,
                                      float* __restrict__ out)
{
    const int tid    = blockIdx.x * blockDim.x + threadIdx.x;
    const int gw     = tid >> 5;
    const int lane   = tid & 31;
    const int stride = (gridDim.x * blockDim.x) >> 5;

    int e = gw;
    if (e >= BATCH) return;

    // Base with the path's "-1" folded in, plus this lane's float4 slice.
    const float4* __restrict__ Wm1 = (const float4*)(W - (size_t)NDIM) + lane;
    const float4* __restrict__ Wl  = (const float4*)W + lane;

    // --- prologue ---
    int2 cv0 = __ldg((const int2*)coll + e);
    int  e1  = e + stride;
    int2 cv1 = make_int2(0, 0);
    if (e1 < BATCH) cv1 = __ldg((const int2*)coll + e1);

    float4 z, w[NPATH];
    {
        z = __ldg(Wl + (size_t)((unsigned)cv0.x + OFFSET) * (NDIM / 4));
        const unsigned b = (unsigned)cv0.y + OFFSET + 1u;
#pragma unroll
        for (int i = 0; i < NPATH; ++i)
            w[i] = __ldg(Wm1 + (size_t)(b >> (DEPTH - i)) * (NDIM / 4));
    }

    for (;;) {
        // prefetch coll two elements ahead
        const int e2 = e1 + stride;
        int2 cv2 = make_int2(0, 0);
        if (e2 < BATCH) cv2 = __ldg((const int2*)coll + e2);

        // --- partial dot products for element e (frees w[], z) ---
        float a[25];
#pragma unroll
        for (int i = 0; i < NPATH; ++i)
            a[i] = w[i].x * z.x + w[i].y * z.y + w[i].z * z.z + w[i].w * z.w;
        a[21] = 0.0f; a[22] = 0.0f; a[24] = 0.0f;

        // --- pruned transpose-reduce, stages 1 and 2 (collapses live set to 6) ---
        {
            const bool hi = (lane & 1) != 0;
#pragma unroll
            for (int k = 0; k < NPATH; k += 2) {
                const float send = hi ? a[k] : a[k + 1];
                const float recv = __shfl_xor_sync(0xFFFFFFFFu, send, 1);
                a[k] = (hi ? a[k + 1] : a[k]) + recv;
            }
        }
        {
            const bool hi = (lane & 2) != 0;
#pragma unroll
            for (int k = 0; k < NPATH; k += 4) {
                const float send = hi ? a[k] : a[k + 2];
                const float recv = __shfl_xor_sync(0xFFFFFFFFu, send, 2);
                a[k] = (hi ? a[k + 2] : a[k]) + recv;
            }
        }

        // --- issue next element's 22-row burst (a[] live set is now small) ---
        const bool have_next = (e1 < BATCH);
        if (have_next) {
            z = __ldg(Wl + (size_t)((unsigned)cv1.x + OFFSET) * (NDIM / 4));
            const unsigned b = (unsigned)cv1.y + OFFSET + 1u;
#pragma unroll
            for (int i = 0; i < NPATH; ++i)
                w[i] = __ldg(Wm1 + (size_t)(b >> (DEPTH - i)) * (NDIM / 4));
        }

        // --- remaining reduce stages (overlap the in-flight burst) ---
        {
            const bool hi = (lane & 4) != 0;
#pragma unroll
            for (int k = 0; k < NPATH; k += 8) {
                const float send = hi ? a[k] : a[k + 4];
                const float recv = __shfl_xor_sync(0xFFFFFFFFu, send, 4);
                a[k] = (hi ? a[k + 4] : a[k]) + recv;
            }
        }
        {
            const bool hi = (lane & 8) != 0;
#pragma unroll
            for (int k = 0; k < NPATH; k += 16) {
                const float send = hi ? a[k] : a[k + 8];
                const float recv = __shfl_xor_sync(0xFFFFFFFFu, send, 8);
                a[k] = (hi ? a[k + 8] : a[k]) + recv;
            }
        }
        {
            const bool hi = (lane & 16) != 0;
            const float send = hi ? a[0] : a[16];
            const float recv = __shfl_xor_sync(0xFFFFFFFFu, send, 16);
            a[0] = (hi ? a[16] : a[0]) + recv;
        }

        // lane l (< 21) holds s_l; one SIMT EX2 covers all levels
        float c = (lane < NPATH) ? (1.0f + __expf(-a[0])) : 1.0f;
#pragma unroll
        for (int o = 16; o > 0; o >>= 1)
            c *= __shfl_xor_sync(0xFFFFFFFFu, c, o);

        if (lane == 0) out[e] = __fdividef(1.0f, c);

        if (!have_next) return;
        e   = e1;
        e1  = e2;
        cv1 = cv2;
    }
}

extern "C" void kernel_launch(void* const* d_in, const int* in_sizes, int n_in,
                              void* d_out, int out_size)
{
    const int*   coll = (const int*)d_in[0];
    const float* W    = (const float*)d_in[1];
    float*       out  = (float*)d_out;

    // 5 blocks/SM x 148 SMs, 4 warps per block; grid-stride inside.
    const int threads = 128;
    const int blocks  = 740;
    BinaryTree_65927747993695_kernel<<<blocks, threads>>>(coll, W, out);
}

// round 6
// speedup vs baseline: 1.8199x; 1.8199x over previous
#include <cuda_runtime.h>
#include <cstdint>

// BinaryTree hierarchical-softmax forward:
//   z = W[leaf(input)], path = 21 root-to-leaf nodes of context vertex
//   out[b] = prod_i sigmoid(dot(W[path_i], z)) = 1 / prod_i (1 + exp(-s_i))
//
// d_in[0]: collocation int32 [65536, 2]
// d_in[1]: W float32 [2097151, 128]
// d_out  : float32 [65536]
//
// Persistent pipelined warps (R4 occupancy config: NO register cap — the
// in-flight 22-row burst must stay register-resident; a 96-reg cap spills it
// to local memory and triples runtime). coll prefetched 2 ahead; pruned
// 23-shuffle transpose-reduce; next burst issued mid-reduce.

#define DEPTH   20
#define NPATH   21
#define OFFSET  1048575u             // (1<<DEPTH)-1
#define NDIM    128
#define BATCH   65536

__global__ __launch_bounds__(128)
void BinaryTree_65927747993695_kernel(const int* __restrict__ coll,
                                      const float* __restrict__ W,
                                      float* __restrict__ out)
{
    const int tid    = blockIdx.x * blockDim.x + threadIdx.x;
    const int gw     = tid >> 5;
    const int lane   = tid & 31;
    const int stride = (gridDim.x * blockDim.x) >> 5;

    int e = gw;
    if (e >= BATCH) return;

    // Base with the path's "-1" folded in, plus this lane's float4 slice.
    const float4* __restrict__ Wm1 = (const float4*)(W - (size_t)NDIM) + lane;
    const float4* __restrict__ Wl  = (const float4*)W + lane;

    // --- prologue ---
    int2 cv0 = __ldg((const int2*)coll + e);
    int  e1  = e + stride;
    int2 cv1 = make_int2(0, 0);
    if (e1 < BATCH) cv1 = __ldg((const int2*)coll + e1);

    float4 z, w[NPATH];
    {
        z = __ldg(Wl + (size_t)((unsigned)cv0.x + OFFSET) * (NDIM / 4));
        const unsigned b = (unsigned)cv0.y + OFFSET + 1u;
#pragma unroll
        for (int i = 0; i < NPATH; ++i)
            w[i] = __ldg(Wm1 + (size_t)(b >> (DEPTH - i)) * (NDIM / 4));
    }

    for (;;) {
        // prefetch coll two elements ahead
        const int e2 = e1 + stride;
        int2 cv2 = make_int2(0, 0);
        if (e2 < BATCH) cv2 = __ldg((const int2*)coll + e2);

        // --- partial dot products for element e (frees w[], z) ---
        float a[25];
#pragma unroll
        for (int i = 0; i < NPATH; ++i)
            a[i] = w[i].x * z.x + w[i].y * z.y + w[i].z * z.z + w[i].w * z.w;
        a[21] = 0.0f; a[22] = 0.0f; a[24] = 0.0f;

        // --- pruned transpose-reduce, stages 1 and 2 (live set 21 -> 6) ---
        {
            const bool hi = (lane & 1) != 0;
#pragma unroll
            for (int k = 0; k < NPATH; k += 2) {
                const float send = hi ? a[k] : a[k + 1];
                const float recv = __shfl_xor_sync(0xFFFFFFFFu, send, 1);
                a[k] = (hi ? a[k + 1] : a[k]) + recv;
            }
        }
        {
            const bool hi = (lane & 2) != 0;
#pragma unroll
            for (int k = 0; k < NPATH; k += 4) {
                const float send = hi ? a[k] : a[k + 2];
                const float recv = __shfl_xor_sync(0xFFFFFFFFu, send, 2);
                a[k] = (hi ? a[k + 2] : a[k]) + recv;
            }
        }

        // --- issue next element's 22-row burst into freed registers ---
        const bool have_next = (e1 < BATCH);
        if (have_next) {
            z = __ldg(Wl + (size_t)((unsigned)cv1.x + OFFSET) * (NDIM / 4));
            const unsigned b = (unsigned)cv1.y + OFFSET + 1u;
#pragma unroll
            for (int i = 0; i < NPATH; ++i)
                w[i] = __ldg(Wm1 + (size_t)(b >> (DEPTH - i)) * (NDIM / 4));
        }

        // --- remaining reduce stages (overlap the in-flight burst) ---
        {
            const bool hi = (lane & 4) != 0;
#pragma unroll
            for (int k = 0; k < NPATH; k += 8) {
                const float send = hi ? a[k] : a[k + 4];
                const float recv = __shfl_xor_sync(0xFFFFFFFFu, send, 4);
                a[k] = (hi ? a[k + 4] : a[k]) + recv;
            }
        }
        {
            const bool hi = (lane & 8) != 0;
#pragma unroll
            for (int k = 0; k < NPATH; k += 16) {
                const float send = hi ? a[k] : a[k + 8];
                const float recv = __shfl_xor_sync(0xFFFFFFFFu, send, 8);
                a[k] = (hi ? a[k + 8] : a[k]) + recv;
            }
        }
        {
            const bool hi = (lane & 16) != 0;
            const float send = hi ? a[0] : a[16];
            const float recv = __shfl_xor_sync(0xFFFFFFFFu, send, 16);
            a[0] = (hi ? a[16] : a[0]) + recv;
        }

        // lane l (< 21) holds s_l; one SIMT EX2 covers all levels
        float c = (lane < NPATH) ? (1.0f + __expf(-a[0])) : 1.0f;
#pragma unroll
        for (int o = 16; o > 0; o >>= 1)
            c *= __shfl_xor_sync(0xFFFFFFFFu, c, o);

        if (lane == 0) out[e] = __fdividef(1.0f, c);

        if (!have_next) return;
        e   = e1;
        e1  = e2;
        cv1 = cv2;
    }
}

extern "C" void kernel_launch(void* const* d_in, const int* in_sizes, int n_in,
                              void* d_out, int out_size)
{
    const int*   coll = (const int*)d_in[0];
    const float* W    = (const float*)d_in[1];
    float*       out  = (float*)d_out;

    // 4 blocks/SM x 148 SMs (R4 config), 4 warps per block; grid-stride inside.
    const int threads = 128;
    const int blocks  = 592;
    BinaryTree_65927747993695_kernel<<<blocks, threads>>>(coll, W, out);
}

// round 7
// speedup vs baseline: 2.0973x; 1.1524x over previous
#include <cuda_runtime.h>
#include <cstdint>

// BinaryTree hierarchical-softmax forward:
//   z = W[leaf(input)], path = 21 root-to-leaf nodes of context vertex
//   out[b] = prod_i sigmoid(dot(W[path_i], z)) = 1 / prod_i (1 + exp(-s_i))
//
// d_in[0]: collocation int32 [65536, 2]
// d_in[1]: W float32 [2097151, 128]
// d_out  : float32 [65536]
//
// Continuous-stream design: 4 elements per warp (8 lanes each, lane owns a
// 64B row slice -> each LDG.128 covers 4 full 128B lines). Levels are
// processed as a stream with a rolling CHUNK=3 window (12 rows in flight at
// all times). Since 21 % 3 == 0 the slot phase is element-invariant, so the
// tail levels of one element prefetch levels 0..2 of the next: the load
// pipe never drains, including across element boundaries. Sigmoids fold
// into a running denominator product (1 EX2 per level, SIMT over 4 elems).
// Grid is sized from measured occupancy -> exactly one resident wave.

#define DEPTH   20
#define NPATH   21
#define OFFSET  1048575u             // (1<<DEPTH)-1
#define BATCH   65536
#define NTASK   (BATCH / 4)          // 16384 warp-tasks (4 elements each)
#define CHUNK   3                    // levels in flight (21 % CHUNK == 0)

__global__ __launch_bounds__(128)
void BinaryTree_65927747993695_kernel(const int* __restrict__ coll,
                                      const float* __restrict__ W,
                                      float* __restrict__ out)
{
    const int tid    = blockIdx.x * blockDim.x + threadIdx.x;
    const int gw     = tid >> 5;
    const int lane   = tid & 31;
    const int sub    = lane >> 3;        // element-in-warp 0..3
    const int l8     = lane & 7;         // lane-in-group 0..7
    const int stride = (gridDim.x * blockDim.x) >> 5;

    int task = gw;
    if (task >= NTASK) return;

    // float4-unit bases; path "-1" folded into Wm1 (node*32 - 32 float4s)
    const float4* __restrict__ Wl  = (const float4*)W + l8;
    const float4* __restrict__ Wm1 = (const float4*)W - 32 + l8;

    int e = task * 4 + sub;
    int2 cv = __ldg((const int2*)coll + e);

    int  task1 = task + stride;
    int2 cv1   = make_int2(0, 0);
    if (task1 < NTASK) cv1 = __ldg((const int2*)coll + task1 * 4 + sub);

    // z for current element (lane's 64B slice = 4 float4)
    float4 z0, z1, z2, z3;
    {
        const float4* zp = Wl + (size_t)((unsigned)cv.x + OFFSET) * 32;
        z0 = __ldg(zp); z1 = __ldg(zp + 8); z2 = __ldg(zp + 16); z3 = __ldg(zp + 24);
    }
    unsigned b = (unsigned)cv.y + OFFSET + 1u;

    // rolling window: CHUNK levels x 4 float4 per lane
    float4 w0[CHUNK], w1[CHUNK], w2[CHUNK], w3[CHUNK];
#pragma unroll
    for (int j = 0; j < CHUNK; ++j) {
        const float4* p = Wm1 + (size_t)(b >> (DEPTH - j)) * 32;
        w0[j] = __ldg(p); w1[j] = __ldg(p + 8); w2[j] = __ldg(p + 16); w3[j] = __ldg(p + 24);
    }

    float denom = 1.0f;

    for (;;) {
        // prefetch coll two tasks ahead
        const int task2 = task1 + stride;
        int2 cv2 = make_int2(0, 0);
        if (task2 < NTASK) cv2 = __ldg((const int2*)coll + task2 * 4 + sub);

        const unsigned bn = (unsigned)cv1.y + OFFSET + 1u;
        const bool have_next = (task1 < NTASK);

#pragma unroll
        for (int i = 0; i < NPATH; ++i) {
            const int s = i % CHUNK;

            // dot of level i's row slice with z (16 FMA)
            float acc = w0[s].x * z0.x + w0[s].y * z0.y + w0[s].z * z0.z + w0[s].w * z0.w
                      + w1[s].x * z1.x + w1[s].y * z1.y + w1[s].z * z1.z + w1[s].w * z1.w
                      + w2[s].x * z2.x + w2[s].y * z2.y + w2[s].z * z2.z + w2[s].w * z2.w
                      + w3[s].x * z3.x + w3[s].y * z3.y + w3[s].z * z3.z + w3[s].w * z3.w;

            // refill the freed slot: level i+CHUNK of current element, or
            // level i-(NPATH-CHUNK) of the next element (phase-invariant
            // because NPATH % CHUNK == 0)
            if (i < NPATH - CHUNK) {
                const float4* p = Wm1 + (size_t)(b >> (DEPTH - (i + CHUNK))) * 32;
                w0[s] = __ldg(p); w1[s] = __ldg(p + 8); w2[s] = __ldg(p + 16); w3[s] = __ldg(p + 24);
            } else if (have_next) {
                const int j = i - (NPATH - CHUNK);      // 0..CHUNK-1
                const float4* p = Wm1 + (size_t)(bn >> (DEPTH - j)) * 32;
                w0[s] = __ldg(p); w1[s] = __ldg(p + 8); w2[s] = __ldg(p + 16); w3[s] = __ldg(p + 24);
            }

            // 3-stage butterfly within the 8-lane group
            acc += __shfl_xor_sync(0xFFFFFFFFu, acc, 4);
            acc += __shfl_xor_sync(0xFFFFFFFFu, acc, 2);
            acc += __shfl_xor_sync(0xFFFFFFFFu, acc, 1);

            denom *= 1.0f + __expf(-acc);
        }

        if (l8 == 0) out[e] = __fdividef(1.0f, denom);
        denom = 1.0f;

        if (!have_next) return;

        // advance to next element; its path rows are already in flight,
        // only z needs loading here
        e = task1 * 4 + sub;
        {
            const float4* zp = Wl + (size_t)((unsigned)cv1.x + OFFSET) * 32;
            z0 = __ldg(zp); z1 = __ldg(zp + 8); z2 = __ldg(zp + 16); z3 = __ldg(zp + 24);
        }
        b     = bn;
        task1 = task2;
        cv1   = cv2;
    }
}

extern "C" void kernel_launch(void* const* d_in, const int* in_sizes, int n_in,
                              void* d_out, int out_size)
{
    const int*   coll = (const int*)d_in[0];
    const float* W    = (const float*)d_in[1];
    float*       out  = (float*)d_out;

    // Size the grid to exactly one resident wave (no straggler waves).
    const int threads = 128;
    int bpsm = 4;
    cudaOccupancyMaxActiveBlocksPerMultiprocessor(
        &bpsm, BinaryTree_65927747993695_kernel, threads, 0);
    if (bpsm < 1) bpsm = 1;
    long long blocks = (long long)bpsm * 148;
    if (blocks > NTASK / 4) blocks = NTASK / 4;   // never exceed task count
    BinaryTree_65927747993695_kernel<<<(int)blocks, threads>>>(coll, W, out);
}

// round 8
// speedup vs baseline: 2.7284x; 1.3009x over previous
#include <cuda_runtime.h>
#include <cstdint>

// BinaryTree hierarchical-softmax forward:
//   z = W[leaf(input)], path = 21 root-to-leaf nodes of context vertex
//   out[b] = prod_i sigmoid(dot(W[path_i], z)) = 1 / prod_i (1 + exp(-s_i))
//
// d_in[0]: collocation int32 [65536, 2]
// d_in[1]: W float32 [2097151, 128]
// d_out  : float32 [65536]
//
// Persistent warp-per-element with full 22-row LDG.128 burst (proven R4
// structure: big bursts beat shallow streaming — scoreboard slack, not
// nominal MLP, is what binds). New: the 21-value cross-lane reduction goes
// through a padded shared-memory transpose (21 STS as partials are computed,
// then lane l reads its row as 8 LDS.128 and sums). This removes the a[32]
// register array and ~60 SEL + 31 SHFL, dropping the register peak so the
// occupancy-sized launcher can fit 5 blocks/SM. NO register cap (a forced
// cap spills the burst and triples runtime — R5).

#define DEPTH   20
#define NPATH   21
#define OFFSET  1048575u             // (1<<DEPTH)-1
#define NDIM    128
#define BATCH   65536
#define PITCH   36                   // words; 16B-aligned rows, low conflicts

__global__ __launch_bounds__(128)
void BinaryTree_65927747993695_kernel(const int* __restrict__ coll,
                                      const float* __restrict__ W,
                                      float* __restrict__ out)
{
    __shared__ float red[4][NPATH * PITCH];

    const int tid    = blockIdx.x * blockDim.x + threadIdx.x;
    const int gw     = tid >> 5;
    const int lane   = tid & 31;
    const int wib    = (threadIdx.x >> 5) & 3;
    const int stride = (gridDim.x * blockDim.x) >> 5;

    int e = gw;
    if (e >= BATCH) return;

    float* __restrict__ row = red[wib];

    // float4-unit bases; path "-1" folded into Wm1; lane slice folded in.
    const float4* __restrict__ Wl  = (const float4*)W + lane;
    const float4* __restrict__ Wm1 = (const float4*)W - (NDIM / 4) + lane;

    // --- prologue ---
    int2 cv0 = __ldg((const int2*)coll + e);
    int  e1  = e + stride;
    int2 cv1 = make_int2(0, 0);
    if (e1 < BATCH) cv1 = __ldg((const int2*)coll + e1);

    float4 z, w[NPATH];
    {
        z = __ldg(Wl + (size_t)((unsigned)cv0.x + OFFSET) * (NDIM / 4));
        const unsigned b = (unsigned)cv0.y + OFFSET + 1u;
#pragma unroll
        for (int i = 0; i < NPATH; ++i)
            w[i] = __ldg(Wm1 + (size_t)(b >> (DEPTH - i)) * (NDIM / 4));
    }

    for (;;) {
        // prefetch coll two elements ahead
        const int e2 = e1 + stride;
        int2 cv2 = make_int2(0, 0);
        if (e2 < BATCH) cv2 = __ldg((const int2*)coll + e2);

        // --- partial dots, stored straight to smem (w[i] freed as we go) ---
#pragma unroll
        for (int i = 0; i < NPATH; ++i) {
            const float s = w[i].x * z.x + w[i].y * z.y + w[i].z * z.z + w[i].w * z.w;
            row[i * PITCH + lane] = s;
        }

        // --- issue next element's 22-row burst into the freed registers ---
        const bool have_next = (e1 < BATCH);
        if (have_next) {
            z = __ldg(Wl + (size_t)((unsigned)cv1.x + OFFSET) * (NDIM / 4));
            const unsigned b = (unsigned)cv1.y + OFFSET + 1u;
#pragma unroll
            for (int i = 0; i < NPATH; ++i)
                w[i] = __ldg(Wm1 + (size_t)(b >> (DEPTH - i)) * (NDIM / 4));
        }

        __syncwarp();

        // --- lane l (<21) sums its level's 32 partials: 8 x LDS.128 ---
        float c = 1.0f;
        if (lane < NPATH) {
            const float4* r4 = (const float4*)(row + lane * PITCH);
            float4 p0 = r4[0], p1 = r4[1], p2 = r4[2], p3 = r4[3];
            float4 p4 = r4[4], p5 = r4[5], p6 = r4[6], p7 = r4[7];
            float s = ((p0.x + p0.y) + (p0.z + p0.w))
                    + ((p1.x + p1.y) + (p1.z + p1.w))
                    + ((p2.x + p2.y) + (p2.z + p2.w))
                    + ((p3.x + p3.y) + (p3.z + p3.w))
                    + ((p4.x + p4.y) + (p4.z + p4.w))
                    + ((p5.x + p5.y) + (p5.z + p5.w))
                    + ((p6.x + p6.y) + (p6.z + p6.w))
                    + ((p7.x + p7.y) + (p7.z + p7.w));
            c = 1.0f + __expf(-s);
        }
        __syncwarp();

        // 5-shuffle product over the warp, then reciprocal
#pragma unroll
        for (int o = 16; o > 0; o >>= 1)
            c *= __shfl_xor_sync(0xFFFFFFFFu, c, o);

        if (lane == 0) out[e] = __fdividef(1.0f, c);

        if (!have_next) return;
        e   = e1;
        e1  = e2;
        cv1 = cv2;
    }
}

extern "C" void kernel_launch(void* const* d_in, const int* in_sizes, int n_in,
                              void* d_out, int out_size)
{
    const int*   coll = (const int*)d_in[0];
    const float* W    = (const float*)d_in[1];
    float*       out  = (float*)d_out;

    // Exactly one resident wave: size grid from measured occupancy.
    const int threads = 128;
    int bpsm = 4;
    cudaOccupancyMaxActiveBlocksPerMultiprocessor(
        &bpsm, BinaryTree_65927747993695_kernel, threads, 0);
    if (bpsm < 1) bpsm = 1;
    long long blocks = (long long)bpsm * 148;
    if (blocks > BATCH / 4) blocks = BATCH / 4;
    BinaryTree_65927747993695_kernel<<<(int)blocks, threads>>>(coll, W, out);
}